// round 1
// baseline (speedup 1.0000x reference)
#include <cuda_runtime.h>

// Cosine-similarity discriminator:
//   out[b, n]     = dot(s_n, h_rl_n)   (rows L2-normalized, eps=1e-12 clamp)
//   out[b, N + n] = dot(s_n, h_fk_n)
// Shapes: s, h_rl, h_fk : [B=8, N=8192, D=512] fp32 ; out : [B, 2N] fp32.
//
// One warp per row. Each lane: 4 float4 loads per tensor (coalesced 512B/warp
// per load), 5 accumulators, warp shuffle reduce, lane 0 writes 2 outputs.

#define D 512
#define NROW_N 8192          // N (inner row count per batch)
#define WARPS_PER_BLOCK 8

__global__ __launch_bounds__(WARPS_PER_BLOCK * 32)
void cosine_pair_kernel(const float* __restrict__ s,
                        const float* __restrict__ h_rl,
                        const float* __restrict__ h_fk,
                        float* __restrict__ out,
                        int total_rows)
{
    const int warp_id = (blockIdx.x * WARPS_PER_BLOCK) + (threadIdx.x >> 5);
    const int lane    = threadIdx.x & 31;
    if (warp_id >= total_rows) return;

    const size_t base = (size_t)warp_id * D;
    const float4* __restrict__ s4  = reinterpret_cast<const float4*>(s    + base);
    const float4* __restrict__ a4  = reinterpret_cast<const float4*>(h_rl + base);
    const float4* __restrict__ b4  = reinterpret_cast<const float4*>(h_fk + base);

    float ss = 0.f, aa = 0.f, bb = 0.f, sa = 0.f, sb = 0.f;

    // D/4 = 128 float4 per row; 32 lanes -> 4 iterations. Front-batch loads
    // for MLP; independent accumulators keep the FMA chain short.
    float4 vs[4], va[4], vb[4];
#pragma unroll
    for (int i = 0; i < 4; ++i) {
        vs[i] = s4[i * 32 + lane];
        va[i] = a4[i * 32 + lane];
        vb[i] = b4[i * 32 + lane];
    }
#pragma unroll
    for (int i = 0; i < 4; ++i) {
        const float4 x = vs[i], y = va[i], z = vb[i];
        ss += x.x * x.x + x.y * x.y + x.z * x.z + x.w * x.w;
        aa += y.x * y.x + y.y * y.y + y.z * y.z + y.w * y.w;
        bb += z.x * z.x + z.y * z.y + z.z * z.z + z.w * z.w;
        sa += x.x * y.x + x.y * y.y + x.z * y.z + x.w * y.w;
        sb += x.x * z.x + x.y * z.y + x.z * z.z * 0.f + x.z * z.z + x.w * z.w;
    }
    // NOTE: the sb line above must be a clean dot; rewrite it correctly:
    // (kept separate to avoid any typo slipping in)
    // -- recompute sb from scratch to be safe:
    sb = 0.f;
#pragma unroll
    for (int i = 0; i < 4; ++i) {
        const float4 x = vs[i], z = vb[i];
        sb += x.x * z.x + x.y * z.y + x.z * z.z + x.w * z.w;
    }

    // Warp butterfly reduction over 5 values.
#pragma unroll
    for (int off = 16; off > 0; off >>= 1) {
        ss += __shfl_xor_sync(0xffffffffu, ss, off);
        aa += __shfl_xor_sync(0xffffffffu, aa, off);
        bb += __shfl_xor_sync(0xffffffffu, bb, off);
        sa += __shfl_xor_sync(0xffffffffu, sa, off);
        sb += __shfl_xor_sync(0xffffffffu, sb, off);
    }

    if (lane == 0) {
        const float eps = 1e-12f;
        const float ns = fmaxf(sqrtf(ss), eps);
        const float na = fmaxf(sqrtf(aa), eps);
        const float nb = fmaxf(sqrtf(bb), eps);
        const float sc_rl = sa / (ns * na);
        const float sc_fk = sb / (ns * nb);

        const int b = warp_id / NROW_N;       // batch index
        const int n = warp_id - b * NROW_N;   // row within batch
        float* obase = out + (size_t)b * (2 * NROW_N);
        obase[n]           = sc_rl;
        obase[NROW_N + n]  = sc_fk;
    }
}

extern "C" void kernel_launch(void* const* d_in, const int* in_sizes, int n_in,
                              void* d_out, int out_size)
{
    const float* s    = (const float*)d_in[0];
    const float* h_rl = (const float*)d_in[1];
    const float* h_fk = (const float*)d_in[2];
    float* out = (float*)d_out;

    const int total_rows = in_sizes[0] / D;   // B*N = 65536
    const int threads = WARPS_PER_BLOCK * 32; // 256
    const int blocks  = (total_rows + WARPS_PER_BLOCK - 1) / WARPS_PER_BLOCK;

    cosine_pair_kernel<<<blocks, threads>>>(s, h_rl, h_fk, out, total_rows);
}